// round 13
// baseline (speedup 1.0000x reference)
#include <cuda_runtime.h>
#include <cuda_fp16.h>
#include <cstdint>
#include <cstddef>

#define HW    9216      // 96*96
#define NCELL (2 * 32 * HW)   // 589824
#define NTILE 9216      // 64 bq * 144 pixel-tiles
#define NSTRM 74        // tile streams (296 CTAs / 4 subs)

// Scratch (device globals — allocation-free per harness rules)
__device__ float g_xenc[(size_t)NCELL * 64];       // conv output, channels-last
__device__ float g_A[(size_t)NCELL * 256];         // 30*(xenc @ W1[0:64] + b1)
__device__ float g_part[(size_t)NTILE * 4 * 64];   // per-(tile,h,nh) partials
__device__ __align__(16) __half g_w2h[256 * 264];  // W2^T fp16, [n][k] pad 264
__device__ __align__(16) __half g_w1h[256 * 72];   // W1[0:64]^T hi fp16
__device__ __align__(16) __half g_w1l[256 * 72];   // W1[0:64]^T lo fp16

// ---------------------------------------------------------------------------
// Helpers
// ---------------------------------------------------------------------------
__device__ __forceinline__ uint32_t smem_u32(const void* p) {
    uint32_t a;
    asm("{ .reg .u64 t; cvta.to.shared.u64 t, %1; cvt.u32.u64 %0, t; }" : "=r"(a) : "l"(p));
    return a;
}
__device__ __forceinline__ void ldsm_x4(uint32_t (&r)[4], uint32_t addr) {
    asm volatile("ldmatrix.sync.aligned.m8n8.x4.shared.b16 {%0,%1,%2,%3}, [%4];"
                 : "=r"(r[0]), "=r"(r[1]), "=r"(r[2]), "=r"(r[3]) : "r"(addr));
}
__device__ __forceinline__ void mma16816(float (&d)[4], const uint32_t (&a)[4],
                                         const uint32_t* b) {
    asm volatile("mma.sync.aligned.m16n8k16.row.col.f32.f16.f16.f32 "
                 "{%0,%1,%2,%3}, {%4,%5,%6,%7}, {%8,%9}, {%0,%1,%2,%3};"
                 : "+f"(d[0]), "+f"(d[1]), "+f"(d[2]), "+f"(d[3])
                 : "r"(a[0]), "r"(a[1]), "r"(a[2]), "r"(a[3]), "r"(b[0]), "r"(b[1]));
}

// ---------------------------------------------------------------------------
// Kernel 1: 3D conv (2 -> 64 channels, 3x3x3, SAME), output channels-last.
// ---------------------------------------------------------------------------
__global__ __launch_bounds__(256) void conv_kernel(
    const float* __restrict__ xr, const float* __restrict__ xi,
    const float* __restrict__ ew, const float* __restrict__ eb)
{
    extern __shared__ float sm[];
    float* ws   = sm;            // 3456
    float* bs   = ws + 3456;     // 64
    float* tile = bs + 64;       // 256 * 65

    int tid = threadIdx.x;
    for (int e = tid; e < 3456; e += 256) ws[e] = ew[e];
    if (tid < 64) bs[tid] = eb[tid];

    int blk = blockIdx.x;
    int bt  = blk / 36;
    int t36 = blk % 36;
    int t   = bt & 31;
    int b   = bt >> 5;
    int pix = t36 * 256 + tid;
    int h   = pix / 96;
    int w   = pix % 96;

    float v[54];
    {
        int e = 0;
        #pragma unroll
        for (int ch = 0; ch < 2; ch++) {
            const float* src = (ch == 0) ? xr : xi;
            #pragma unroll
            for (int dt = -1; dt <= 1; dt++) {
                int  tt  = t + dt;
                bool okt = (tt >= 0) && (tt < 32);
                #pragma unroll
                for (int dh = -1; dh <= 1; dh++) {
                    int  hh  = h + dh;
                    bool okh = okt && (hh >= 0) && (hh < 96);
                    #pragma unroll
                    for (int dw = -1; dw <= 1; dw++) {
                        int  ww = w + dw;
                        bool ok = okh && (ww >= 0) && (ww < 96);
                        v[e++] = ok ? src[(((size_t)(b * 32 + tt)) * 96 + hh) * 96 + ww] : 0.0f;
                    }
                }
            }
        }
    }
    __syncthreads();

    #pragma unroll 4
    for (int c = 0; c < 64; c++) {
        float acc = bs[c];
        #pragma unroll
        for (int q = 0; q < 54; q++) acc = fmaf(v[q], ws[c * 54 + q], acc);
        tile[tid * 65 + c] = acc;
    }
    __syncthreads();

    size_t outbase = ((size_t)bt * HW + (size_t)t36 * 256) * 64;
    for (int e = tid; e < 256 * 64; e += 256) {
        int p = e >> 6, c = e & 63;
        g_xenc[outbase + e] = tile[p * 65 + c];
    }
}

// ---------------------------------------------------------------------------
// Prep kernels: transpose weights into fp16 [n][k] padded layouts
// ---------------------------------------------------------------------------
__global__ void prep_w2(const float* __restrict__ W2)
{
    int idx = blockIdx.x * 256 + threadIdx.x;   // 65536
    int n = idx >> 8, k = idx & 255;
    g_w2h[n * 264 + k] = __float2half_rn(W2[k * 256 + n]);
}
__global__ void prep_w1(const float* __restrict__ W1)
{
    int n = blockIdx.x, k = threadIdx.x;        // 256 x 72
    float v = (k < 64) ? W1[k * 256 + n] : 0.0f;
    __half hi = __float2half_rn(v);
    g_w1h[n * 72 + k] = hi;
    g_w1l[n * 72 + k] = __float2half_rn(v - __half2float(hi));
}

// ---------------------------------------------------------------------------
// Kernel 2 (HMMA, persistent, 512 thr, prefetched): A = 30*(xenc@W1[0:64]+b1)
// ---------------------------------------------------------------------------
#define PROW 144              // bytes per [.,72-half] row
#define SMP_WH 0              // 256*144 = 36864
#define SMP_WL 36864
#define SMP_XH 73728          // 64*144 = 9216
#define SMP_XL 82944
#define SMP_TOT 92160

__global__ __launch_bounds__(512, 1) void proj_kernel(
    const float* __restrict__ b1)
{
    extern __shared__ char smem[];
    const uint32_t sb = smem_u32(smem);
    int tid  = threadIdx.x;
    int w    = tid >> 5;
    int lane = tid & 31;

    // Stage W1 hi/lo (resident)
    {
        const float4* s0 = (const float4*)g_w1h;
        const float4* s1 = (const float4*)g_w1l;
        float4* d0 = (float4*)(smem + SMP_WH);
        float4* d1 = (float4*)(smem + SMP_WL);
        for (int i = tid; i < 256 * 144 / 16; i += 512) { d0[i] = s0[i]; d1[i] = s1[i]; }
    }

    const int wm = (w & 3) * 16;       // 4 m-groups x 16 rows
    const int wn = (w >> 2) * 64;      // 4 n-groups x 64 cols

    float b1r[16];
    #pragma unroll
    for (int q = 0; q < 16; q++)
        b1r[q] = b1[wn + (q >> 1) * 8 + (lane & 3) * 2 + (q & 1)];

    const uint32_t a_toff = (uint32_t)(wm + (lane & 15)) * PROW + (uint32_t)(lane >> 4) * 16;
    const uint32_t b_toff = (uint32_t)(wn + (lane & 7) + ((lane >> 4) & 1) * 8) * PROW
                          + (uint32_t)((lane >> 3) & 1) * 16;

    const int lrow = tid >> 3;             // cell row this thread loads (64 rows)
    const int lk   = (tid & 7) * 8;        // 8 k values
    __syncthreads();

    // Prologue prefetch
    float4 v0, v1;
    {
        const float4* src = (const float4*)(g_xenc + ((size_t)blockIdx.x * 64 + lrow) * 64 + lk);
        v0 = src[0]; v1 = src[1];
    }

    for (int tile = blockIdx.x; tile < 9216; tile += 148) {
        size_t cell0 = (size_t)tile * 64;

        // Split held regs -> smem
        {
            float vv[8] = {v0.x, v0.y, v0.z, v0.w, v1.x, v1.y, v1.z, v1.w};
            uint32_t hv[4], lv[4];
            #pragma unroll
            for (int p = 0; p < 4; p++) {
                __half h0 = __float2half_rn(vv[2*p]),   h1 = __float2half_rn(vv[2*p+1]);
                __half l0 = __float2half_rn(vv[2*p]   - __half2float(h0));
                __half l1 = __float2half_rn(vv[2*p+1] - __half2float(h1));
                __half2 ph = __halves2half2(h0, h1), pl = __halves2half2(l0, l1);
                hv[p] = *(uint32_t*)&ph;  lv[p] = *(uint32_t*)&pl;
            }
            *(uint4*)(smem + SMP_XH + lrow * PROW + lk * 2) = make_uint4(hv[0], hv[1], hv[2], hv[3]);
            *(uint4*)(smem + SMP_XL + lrow * PROW + lk * 2) = make_uint4(lv[0], lv[1], lv[2], lv[3]);
        }
        __syncthreads();

        // Prefetch next tile while GEMM runs
        int ntile = tile + 148;
        if (ntile < 9216) {
            const float4* src = (const float4*)(g_xenc + ((size_t)ntile * 64 + lrow) * 64 + lk);
            v0 = src[0]; v1 = src[1];
        }

        float acc[8][4];
        #pragma unroll
        for (int nt = 0; nt < 8; nt++)
            #pragma unroll
            for (int c = 0; c < 4; c++) acc[nt][c] = 0.0f;

        const uint32_t abase[3] = {sb + SMP_XH, sb + SMP_XL, sb + SMP_XH};
        const uint32_t bbase[3] = {sb + SMP_WH, sb + SMP_WH, sb + SMP_WL};
        #pragma unroll
        for (int s = 0; s < 3; s++) {
            uint32_t a_addr = abase[s] + a_toff;
            uint32_t b_addr = bbase[s] + b_toff;
            #pragma unroll
            for (int ks = 0; ks < 4; ks++) {
                uint32_t af[4];
                ldsm_x4(af, a_addr);
                #pragma unroll
                for (int np = 0; np < 4; np++) {
                    uint32_t bf[4];
                    ldsm_x4(bf, b_addr + np * 16 * PROW);
                    mma16816(acc[np * 2 + 0], af, bf + 0);
                    mma16816(acc[np * 2 + 1], af, bf + 2);
                }
                a_addr += 32;
                b_addr += 32;
            }
        }

        // Epilogue: A = 30*(z1 + b1), direct STG.64
        {
            int r0 = wm + (lane >> 2);
            #pragma unroll
            for (int nt = 0; nt < 8; nt++) {
                int n0 = wn + nt * 8 + (lane & 3) * 2;
                float2 o0, o1;
                o0.x = 30.0f * (acc[nt][0] + b1r[nt*2+0]);
                o0.y = 30.0f * (acc[nt][1] + b1r[nt*2+1]);
                o1.x = 30.0f * (acc[nt][2] + b1r[nt*2+0]);
                o1.y = 30.0f * (acc[nt][3] + b1r[nt*2+1]);
                *(float2*)&g_A[(cell0 + r0)     * 256 + n0] = o0;
                *(float2*)&g_A[(cell0 + r0 + 8) * 256 + n0] = o1;
            }
        }
        __syncthreads();
    }
}

// ---------------------------------------------------------------------------
// Kernel 3: persistent HMMA SIREN, 296 CTAs (2/SM), 256 thr.
// Each CTA has FIXED (h, nh) = (blockIdx.x&3): unit GEMM M=64px, N=128, K=256.
// W2 n-half resident (67.6KB); A single buffer (33.8KB) => 102KB/CTA.
// Writes coeff-scaled partials to g_part; combine_kernel sums 4 + b3.
// ---------------------------------------------------------------------------
#define AROW    528           // bytes per [.,264-half] row
#define SMM_W2  0             // 128*528 = 67584
#define SMM_A   67584         // 64*528  = 33792
#define SMM_W1T 101376        // 1024
#define SMM_B2S 102400        // 512 (128 floats)
#define SMM_W3S 102912        // 512
#define SMM_SLOT 103424       // 1024 (256 floats)
#define SMM_TOT 104448

struct TP { size_t slice; float coeff, ctc; int tile, pix0; };

__device__ __forceinline__ TP make_tp(const float* __restrict__ tcoord, int tile, int h)
{
    TP t;
    t.tile = tile;
    int bq  = tile & 63;
    t.pix0  = (tile >> 6) * 64;
    int b = bq >> 5;
    float tc = tcoord[bq];
    tc = fminf(fmaxf(tc, -1.0f), 1.0f - 1e-6f);
    const float df = 2.0f / 31.0f;
    int ti = (int)floorf((tc + 1.0f) / df);
    float tau = (tc - (-1.0f + (float)ti * df)) / df;
    t.coeff = h ? tau : (1.0f - tau);
    t.ctc   = 30.0f * tc;
    t.slice = (size_t)(b * 32 + ti + h);
    return t;
}

__device__ __forceinline__ void p1_load8(float4 (&r)[8], size_t slice, int pix0,
                                         int row, int kbase)
{
    const float4* s4 = (const float4*)(g_A + (slice * HW + pix0 + row) * 256 + kbase);
    #pragma unroll
    for (int j = 0; j < 8; j++) r[j] = s4[j];
}

__device__ __forceinline__ void p1_sts8(char* __restrict__ abuf,
    const float* __restrict__ w1t, float ctc, int row, int kbase,
    const float4 (&a4)[8])
{
    char* hb = abuf + row * AROW + kbase * 2;
    #pragma unroll
    for (int j = 0; j < 4; j++) {
        float4 a0 = a4[2*j], a1 = a4[2*j+1];
        const float4 w0  = *(const float4*)&w1t[kbase + 8*j];
        const float4 w1v = *(const float4*)&w1t[kbase + 8*j + 4];
        float s[8];
        s[0] = __sinf(fmaf(ctc, w0.x,  a0.x));
        s[1] = __sinf(fmaf(ctc, w0.y,  a0.y));
        s[2] = __sinf(fmaf(ctc, w0.z,  a0.z));
        s[3] = __sinf(fmaf(ctc, w0.w,  a0.w));
        s[4] = __sinf(fmaf(ctc, w1v.x, a1.x));
        s[5] = __sinf(fmaf(ctc, w1v.y, a1.y));
        s[6] = __sinf(fmaf(ctc, w1v.z, a1.z));
        s[7] = __sinf(fmaf(ctc, w1v.w, a1.w));
        uint32_t hv[4];
        #pragma unroll
        for (int p = 0; p < 4; p++) {
            __half2 ph = __halves2half2(__float2half_rn(s[2*p]),
                                        __float2half_rn(s[2*p+1]));
            hv[p] = *(uint32_t*)&ph;
        }
        *(uint4*)(hb + j * 16) = make_uint4(hv[0], hv[1], hv[2], hv[3]);
    }
}

__global__ __launch_bounds__(256, 2) void main_kernel(
    const float* __restrict__ tcoord, const float* __restrict__ W1,
    const float* __restrict__ b2, const float* __restrict__ W3)
{
    extern __shared__ char smem[];
    const uint32_t sb = smem_u32(smem);
    int tid  = threadIdx.x;
    int w    = tid >> 5;
    int lane = tid & 31;

    const int sub  = blockIdx.x & 3;
    const int strm = blockIdx.x >> 2;
    const int h    = sub >> 1;
    const int nh   = sub & 1;

    // Stage W2 n-half (resident) + tables
    {
        const float4* src = (const float4*)(g_w2h + (size_t)nh * 128 * 264);
        float4*       dst = (float4*)(smem + SMM_W2);
        for (int i = tid; i < 128 * 528 / 16; i += 256) dst[i] = src[i];
    }
    float* w1t   = (float*)(smem + SMM_W1T);
    float* b2s   = (float*)(smem + SMM_B2S);
    float* w3s   = (float*)(smem + SMM_W3S);
    float* slots = (float*)(smem + SMM_SLOT);
    if (tid < 256) w1t[tid] = W1[64 * 256 + tid];
    if (tid < 128) {
        b2s[tid] = 30.0f * b2[nh * 128 + tid];
        w3s[tid] = W3[nh * 128 + tid];
    }
    __syncthreads();

    const int wm = (w & 1) * 32;       // 2 m-groups x 32 rows
    const int wn = (w >> 1) * 32;      // 4 n-groups x 32 cols (local)
    const int ng = w >> 1;

    const uint32_t a_toff = (uint32_t)(wm + (lane & 15)) * AROW + (uint32_t)(lane >> 4) * 16;
    const uint32_t b_toff = (uint32_t)(wn + (lane & 7) + ((lane >> 4) & 1) * 8) * AROW
                          + (uint32_t)((lane >> 3) & 1) * 16;
    const uint32_t a_base = sb + SMM_A + a_toff;
    const uint32_t b_base = sb + SMM_W2 + b_toff;

    const int p1row = tid >> 2;          // 64 rows, 4 thr/row
    const int p1k   = (tid & 3) * 64;    // 64 k values per thread

    int tile = strm;
    TP cur = make_tp(tcoord, tile, h);
    float4 lo[8];
    p1_load8(lo, cur.slice, cur.pix0, p1row, p1k);

    while (true) {
        // ---- phase 1: sin(A + ctc*w1) -> fp16 -> A smem ----
        {
            float4 hi[8];
            p1_load8(hi, cur.slice, cur.pix0, p1row, p1k + 32);
            p1_sts8(smem + SMM_A, w1t, cur.ctc, p1row, p1k,      lo);
            p1_sts8(smem + SMM_A, w1t, cur.ctc, p1row, p1k + 32, hi);
        }
        __syncthreads();

        // ---- GEMM: M=64, N=128(local), K=256 ----
        float acc[2][4][4];
        #pragma unroll
        for (int mt = 0; mt < 2; mt++)
            #pragma unroll
            for (int nt = 0; nt < 4; nt++)
                #pragma unroll
                for (int c = 0; c < 4; c++) acc[mt][nt][c] = 0.0f;

        {
            uint32_t aaddr = a_base, baddr = b_base;
            #pragma unroll 4
            for (int ks = 0; ks < 16; ks++) {
                uint32_t af0[4], af1[4], bf0[4], bf1[4];
                ldsm_x4(af0, aaddr);
                ldsm_x4(af1, aaddr + 16 * AROW);
                ldsm_x4(bf0, baddr);
                ldsm_x4(bf1, baddr + 16 * AROW);
                mma16816(acc[0][0], af0, bf0 + 0);
                mma16816(acc[0][1], af0, bf0 + 2);
                mma16816(acc[0][2], af0, bf1 + 0);
                mma16816(acc[0][3], af0, bf1 + 2);
                mma16816(acc[1][0], af1, bf0 + 0);
                mma16816(acc[1][1], af1, bf0 + 2);
                mma16816(acc[1][2], af1, bf1 + 0);
                mma16816(acc[1][3], af1, bf1 + 2);
                aaddr += 32;
                baddr += 32;
            }
        }

        // ---- prefetch next unit's first A chunk (hidden by epilogue MUFU) ----
        int ntile = tile + NSTRM;
        bool more = (ntile < NTILE);
        TP nxt;
        if (more) {
            nxt = make_tp(tcoord, ntile, h);
            p1_load8(lo, nxt.slice, nxt.pix0, p1row, p1k);
        }

        // ---- epilogue: sin(30z + 30b2).W3 partial dot, reduce ----
        float p[2][2];
        #pragma unroll
        for (int mt = 0; mt < 2; mt++)
            #pragma unroll
            for (int rh = 0; rh < 2; rh++) {
                float s = 0.0f;
                #pragma unroll
                for (int nt = 0; nt < 4; nt++) {
                    int nl = wn + nt * 8 + (lane & 3) * 2;
                    int c0 = rh * 2;
                    s = fmaf(__sinf(fmaf(30.0f, acc[mt][nt][c0],     b2s[nl]    )), w3s[nl],     s);
                    s = fmaf(__sinf(fmaf(30.0f, acc[mt][nt][c0 + 1], b2s[nl + 1])), w3s[nl + 1], s);
                }
                p[mt][rh] = s;
            }
        #pragma unroll
        for (int msk = 1; msk < 4; msk <<= 1) {
            #pragma unroll
            for (int mt = 0; mt < 2; mt++)
                #pragma unroll
                for (int rh = 0; rh < 2; rh++)
                    p[mt][rh] += __shfl_xor_sync(0xffffffffu, p[mt][rh], msk);
        }
        if ((lane & 3) == 0) {
            #pragma unroll
            for (int mt = 0; mt < 2; mt++)
                #pragma unroll
                for (int rh = 0; rh < 2; rh++)
                    slots[ng * 64 + wm + mt * 16 + rh * 8 + (lane >> 2)] = p[mt][rh];
        }
        __syncthreads();

        if (tid < 64) {
            float z = slots[tid] + slots[64 + tid] + slots[128 + tid] + slots[192 + tid];
            g_part[((size_t)tile * 4 + sub) * 64 + tid] = cur.coeff * z;
        }

        if (!more) break;
        cur = nxt;
        tile = ntile;
    }
}

// ---------------------------------------------------------------------------
// Kernel 4: combine partials: out = sum of 4 unit partials + b3
// ---------------------------------------------------------------------------
__global__ void combine_kernel(const float* __restrict__ b3, float* __restrict__ out)
{
    int e = blockIdx.x * 256 + threadIdx.x;     // 589824 outputs
    int bq  = e / HW;
    int rem = e - bq * HW;
    int pt  = rem >> 6, px = rem & 63;
    size_t base = ((size_t)(pt * 64 + bq) * 4) * 64 + px;
    out[e] = g_part[base] + g_part[base + 64] + g_part[base + 128]
           + g_part[base + 192] + b3[0];
}

// ---------------------------------------------------------------------------
extern "C" void kernel_launch(void* const* d_in, const int* in_sizes, int n_in,
                              void* d_out, int out_size)
{
    const float* x_real  = (const float*)d_in[0];
    const float* x_imag  = (const float*)d_in[1];
    const float* t_coord = (const float*)d_in[2];
    const float* enc_w   = (const float*)d_in[3];
    const float* enc_b   = (const float*)d_in[4];
    const float* W1      = (const float*)d_in[5];
    const float* b1      = (const float*)d_in[6];
    const float* W2      = (const float*)d_in[7];
    const float* b2      = (const float*)d_in[8];
    const float* W3      = (const float*)d_in[9];
    const float* b3      = (const float*)d_in[10];
    float*       out     = (float*)d_out;

    size_t smem1 = (3456 + 64 + 256 * 65) * sizeof(float);
    cudaFuncSetAttribute(conv_kernel, cudaFuncAttributeMaxDynamicSharedMemorySize, (int)smem1);
    cudaFuncSetAttribute(proj_kernel, cudaFuncAttributeMaxDynamicSharedMemorySize, SMP_TOT);
    cudaFuncSetAttribute(main_kernel, cudaFuncAttributeMaxDynamicSharedMemorySize, SMM_TOT);

    prep_w2<<<256, 256>>>(W2);
    prep_w1<<<256, 72>>>(W1);
    conv_kernel<<<2304, 256, smem1>>>(x_real, x_imag, enc_w, enc_b);
    proj_kernel<<<148, 512, SMP_TOT>>>(b1);
    main_kernel<<<296, 256, SMM_TOT>>>(t_coord, W1, b2, W3);
    combine_kernel<<<2304, 256>>>(b3, out);
}

// round 14
// speedup vs baseline: 1.2669x; 1.2669x over previous
#include <cuda_runtime.h>
#include <cuda_fp16.h>
#include <cstdint>
#include <cstddef>

#define HW    9216      // 96*96
#define NCELL (2 * 32 * HW)   // 589824

// Scratch (device globals — allocation-free per harness rules)
__device__ float g_xenc[(size_t)NCELL * 64];       // conv output, channels-last
__device__ float g_A[(size_t)NCELL * 256];         // 30*(xenc @ W1[0:64] + b1)
__device__ __align__(16) __half g_w2h[256 * 264];  // W2^T fp16, [n][k] pad 264
__device__ __align__(16) __half g_w1h[256 * 72];   // W1[0:64]^T hi fp16
__device__ __align__(16) __half g_w1l[256 * 72];   // W1[0:64]^T lo fp16

// ---------------------------------------------------------------------------
// Helpers
// ---------------------------------------------------------------------------
__device__ __forceinline__ uint32_t smem_u32(const void* p) {
    uint32_t a;
    asm("{ .reg .u64 t; cvta.to.shared.u64 t, %1; cvt.u32.u64 %0, t; }" : "=r"(a) : "l"(p));
    return a;
}
__device__ __forceinline__ void ldsm_x4(uint32_t (&r)[4], uint32_t addr) {
    asm volatile("ldmatrix.sync.aligned.m8n8.x4.shared.b16 {%0,%1,%2,%3}, [%4];"
                 : "=r"(r[0]), "=r"(r[1]), "=r"(r[2]), "=r"(r[3]) : "r"(addr));
}
__device__ __forceinline__ void mma16816(float (&d)[4], const uint32_t (&a)[4],
                                         const uint32_t* b) {
    asm volatile("mma.sync.aligned.m16n8k16.row.col.f32.f16.f16.f32 "
                 "{%0,%1,%2,%3}, {%4,%5,%6,%7}, {%8,%9}, {%0,%1,%2,%3};"
                 : "+f"(d[0]), "+f"(d[1]), "+f"(d[2]), "+f"(d[3])
                 : "r"(a[0]), "r"(a[1]), "r"(a[2]), "r"(a[3]), "r"(b[0]), "r"(b[1]));
}

// ---------------------------------------------------------------------------
// Kernel 1: 3D conv (2 -> 64 channels, 3x3x3, SAME), output channels-last.
// ---------------------------------------------------------------------------
__global__ __launch_bounds__(256) void conv_kernel(
    const float* __restrict__ xr, const float* __restrict__ xi,
    const float* __restrict__ ew, const float* __restrict__ eb)
{
    extern __shared__ float sm[];
    float* ws   = sm;            // 3456
    float* bs   = ws + 3456;     // 64
    float* tile = bs + 64;       // 256 * 65

    int tid = threadIdx.x;
    for (int e = tid; e < 3456; e += 256) ws[e] = ew[e];
    if (tid < 64) bs[tid] = eb[tid];

    int blk = blockIdx.x;
    int bt  = blk / 36;
    int t36 = blk % 36;
    int t   = bt & 31;
    int b   = bt >> 5;
    int pix = t36 * 256 + tid;
    int h   = pix / 96;
    int w   = pix % 96;

    float v[54];
    {
        int e = 0;
        #pragma unroll
        for (int ch = 0; ch < 2; ch++) {
            const float* src = (ch == 0) ? xr : xi;
            #pragma unroll
            for (int dt = -1; dt <= 1; dt++) {
                int  tt  = t + dt;
                bool okt = (tt >= 0) && (tt < 32);
                #pragma unroll
                for (int dh = -1; dh <= 1; dh++) {
                    int  hh  = h + dh;
                    bool okh = okt && (hh >= 0) && (hh < 96);
                    #pragma unroll
                    for (int dw = -1; dw <= 1; dw++) {
                        int  ww = w + dw;
                        bool ok = okh && (ww >= 0) && (ww < 96);
                        v[e++] = ok ? src[(((size_t)(b * 32 + tt)) * 96 + hh) * 96 + ww] : 0.0f;
                    }
                }
            }
        }
    }
    __syncthreads();

    #pragma unroll 4
    for (int c = 0; c < 64; c++) {
        float acc = bs[c];
        #pragma unroll
        for (int q = 0; q < 54; q++) acc = fmaf(v[q], ws[c * 54 + q], acc);
        tile[tid * 65 + c] = acc;
    }
    __syncthreads();

    size_t outbase = ((size_t)bt * HW + (size_t)t36 * 256) * 64;
    for (int e = tid; e < 256 * 64; e += 256) {
        int p = e >> 6, c = e & 63;
        g_xenc[outbase + e] = tile[p * 65 + c];
    }
}

// ---------------------------------------------------------------------------
// Prep kernels: transpose weights into fp16 [n][k] padded layouts
// ---------------------------------------------------------------------------
__global__ void prep_w2(const float* __restrict__ W2)
{
    int idx = blockIdx.x * 256 + threadIdx.x;   // 65536
    int n = idx >> 8, k = idx & 255;
    g_w2h[n * 264 + k] = __float2half_rn(W2[k * 256 + n]);
}
__global__ void prep_w1(const float* __restrict__ W1)
{
    int n = blockIdx.x, k = threadIdx.x;        // 256 x 72
    float v = (k < 64) ? W1[k * 256 + n] : 0.0f;
    __half hi = __float2half_rn(v);
    g_w1h[n * 72 + k] = hi;
    g_w1l[n * 72 + k] = __float2half_rn(v - __half2float(hi));
}

// ---------------------------------------------------------------------------
// Kernel 2 (HMMA, persistent, 512 thr, prefetched): A = 30*(xenc@W1[0:64]+b1)
// ---------------------------------------------------------------------------
#define PROW 144              // bytes per [.,72-half] row
#define SMP_WH 0              // 256*144 = 36864
#define SMP_WL 36864
#define SMP_XH 73728          // 64*144 = 9216
#define SMP_XL 82944
#define SMP_TOT 92160

__global__ __launch_bounds__(512, 1) void proj_kernel(
    const float* __restrict__ b1)
{
    extern __shared__ char smem[];
    const uint32_t sb = smem_u32(smem);
    int tid  = threadIdx.x;
    int w    = tid >> 5;
    int lane = tid & 31;

    // Stage W1 hi/lo (resident)
    {
        const float4* s0 = (const float4*)g_w1h;
        const float4* s1 = (const float4*)g_w1l;
        float4* d0 = (float4*)(smem + SMP_WH);
        float4* d1 = (float4*)(smem + SMP_WL);
        for (int i = tid; i < 256 * 144 / 16; i += 512) { d0[i] = s0[i]; d1[i] = s1[i]; }
    }

    const int wm = (w & 3) * 16;       // 4 m-groups x 16 rows
    const int wn = (w >> 2) * 64;      // 4 n-groups x 64 cols

    float b1r[16];
    #pragma unroll
    for (int q = 0; q < 16; q++)
        b1r[q] = b1[wn + (q >> 1) * 8 + (lane & 3) * 2 + (q & 1)];

    const uint32_t a_toff = (uint32_t)(wm + (lane & 15)) * PROW + (uint32_t)(lane >> 4) * 16;
    const uint32_t b_toff = (uint32_t)(wn + (lane & 7) + ((lane >> 4) & 1) * 8) * PROW
                          + (uint32_t)((lane >> 3) & 1) * 16;

    const int lrow = tid >> 3;             // cell row this thread loads (64 rows)
    const int lk   = (tid & 7) * 8;        // 8 k values
    __syncthreads();

    // Prologue prefetch
    float4 v0, v1;
    {
        const float4* src = (const float4*)(g_xenc + ((size_t)blockIdx.x * 64 + lrow) * 64 + lk);
        v0 = src[0]; v1 = src[1];
    }

    for (int tile = blockIdx.x; tile < 9216; tile += 148) {
        size_t cell0 = (size_t)tile * 64;

        // Split held regs -> smem
        {
            float vv[8] = {v0.x, v0.y, v0.z, v0.w, v1.x, v1.y, v1.z, v1.w};
            uint32_t hv[4], lv[4];
            #pragma unroll
            for (int p = 0; p < 4; p++) {
                __half h0 = __float2half_rn(vv[2*p]),   h1 = __float2half_rn(vv[2*p+1]);
                __half l0 = __float2half_rn(vv[2*p]   - __half2float(h0));
                __half l1 = __float2half_rn(vv[2*p+1] - __half2float(h1));
                __half2 ph = __halves2half2(h0, h1), pl = __halves2half2(l0, l1);
                hv[p] = *(uint32_t*)&ph;  lv[p] = *(uint32_t*)&pl;
            }
            *(uint4*)(smem + SMP_XH + lrow * PROW + lk * 2) = make_uint4(hv[0], hv[1], hv[2], hv[3]);
            *(uint4*)(smem + SMP_XL + lrow * PROW + lk * 2) = make_uint4(lv[0], lv[1], lv[2], lv[3]);
        }
        __syncthreads();

        // Prefetch next tile while GEMM runs
        int ntile = tile + 148;
        if (ntile < 9216) {
            const float4* src = (const float4*)(g_xenc + ((size_t)ntile * 64 + lrow) * 64 + lk);
            v0 = src[0]; v1 = src[1];
        }

        float acc[8][4];
        #pragma unroll
        for (int nt = 0; nt < 8; nt++)
            #pragma unroll
            for (int c = 0; c < 4; c++) acc[nt][c] = 0.0f;

        const uint32_t abase[3] = {sb + SMP_XH, sb + SMP_XL, sb + SMP_XH};
        const uint32_t bbase[3] = {sb + SMP_WH, sb + SMP_WH, sb + SMP_WL};
        #pragma unroll
        for (int s = 0; s < 3; s++) {
            uint32_t a_addr = abase[s] + a_toff;
            uint32_t b_addr = bbase[s] + b_toff;
            #pragma unroll
            for (int ks = 0; ks < 4; ks++) {
                uint32_t af[4];
                ldsm_x4(af, a_addr);
                #pragma unroll
                for (int np = 0; np < 4; np++) {
                    uint32_t bf[4];
                    ldsm_x4(bf, b_addr + np * 16 * PROW);
                    mma16816(acc[np * 2 + 0], af, bf + 0);
                    mma16816(acc[np * 2 + 1], af, bf + 2);
                }
                a_addr += 32;
                b_addr += 32;
            }
        }

        // Epilogue: A = 30*(z1 + b1), direct STG.64
        {
            int r0 = wm + (lane >> 2);
            #pragma unroll
            for (int nt = 0; nt < 8; nt++) {
                int n0 = wn + nt * 8 + (lane & 3) * 2;
                float2 o0, o1;
                o0.x = 30.0f * (acc[nt][0] + b1r[nt*2+0]);
                o0.y = 30.0f * (acc[nt][1] + b1r[nt*2+1]);
                o1.x = 30.0f * (acc[nt][2] + b1r[nt*2+0]);
                o1.y = 30.0f * (acc[nt][3] + b1r[nt*2+1]);
                *(float2*)&g_A[(cell0 + r0)     * 256 + n0] = o0;
                *(float2*)&g_A[(cell0 + r0 + 8) * 256 + n0] = o1;
            }
        }
        __syncthreads();
    }
}

// ---------------------------------------------------------------------------
// Kernel 3: persistent HMMA SIREN (256 thr, warp tile 32x64), phase-1 of the
// NEXT unit interleaved INTO the GEMM K-loop (sin/LSU fill HMMA issue gaps).
// Unit = (tile, h). Buffers alternate per unit; slots parity per tile.
// ---------------------------------------------------------------------------
#define AROW   528            // bytes per [.,264-half] row
#define SM_B    0             // 256*528 = 135168
#define SM_A0   135168        // 64*528  =  33792
#define SM_A1   168960        // 64*528  =  33792
#define SM_W1T  202752        // 1024
#define SM_B2S  203776        // 1024
#define SM_W3S  204800        // 1024
#define SM_SLOT 205824        // 2*512*4 = 4096
#define SM_TOT  209920

struct TP { size_t slice; float tau, ctc; int bq, pix0; };

__device__ __forceinline__ TP make_tp(const float* __restrict__ tcoord, int tile)
{
    TP t;
    t.bq  = tile & 63;
    t.pix0 = (tile >> 6) * 64;
    int b = t.bq >> 5;
    float tc = tcoord[t.bq];
    tc = fminf(fmaxf(tc, -1.0f), 1.0f - 1e-6f);
    const float df = 2.0f / 31.0f;
    int ti = (int)floorf((tc + 1.0f) / df);
    t.tau = (tc - (-1.0f + (float)ti * df)) / df;
    t.ctc = 30.0f * tc;
    t.slice = (size_t)(b * 32 + ti);
    return t;
}

__device__ __forceinline__ void p1_load(float4 (&r)[16], size_t slice, int pix0,
                                        int p1row, int p1k)
{
    const float4* s4 = (const float4*)(g_A + (slice * HW + pix0 + p1row) * 256 + p1k);
    #pragma unroll
    for (int j = 0; j < 16; j++) r[j] = s4[j];
}

// One 4-value phase-1 chunk: sin(A + ctc*w1) -> 2x half2 -> 8B STS
__device__ __forceinline__ void p1_chunk(char* __restrict__ wbase,
    const float* __restrict__ w1t, float ctc, int p1k, int j, const float4& a0)
{
    const float4 w0 = *(const float4*)&w1t[p1k + 4 * j];
    float s0 = __sinf(fmaf(ctc, w0.x, a0.x));
    float s1 = __sinf(fmaf(ctc, w0.y, a0.y));
    float s2 = __sinf(fmaf(ctc, w0.z, a0.z));
    float s3 = __sinf(fmaf(ctc, w0.w, a0.w));
    __half2 ph0 = __halves2half2(__float2half_rn(s0), __float2half_rn(s1));
    __half2 ph1 = __halves2half2(__float2half_rn(s2), __float2half_rn(s3));
    *(uint2*)(wbase + j * 8) = make_uint2(*(uint32_t*)&ph0, *(uint32_t*)&ph1);
}

__global__ __launch_bounds__(256, 1) void main_kernel(
    const float* __restrict__ tcoord, const float* __restrict__ W1,
    const float* __restrict__ b2, const float* __restrict__ W3,
    const float* __restrict__ b3, float* __restrict__ out)
{
    extern __shared__ char smem[];
    const uint32_t sb = smem_u32(smem);
    int tid  = threadIdx.x;
    int w    = tid >> 5;
    int lane = tid & 31;

    // Stage W2 fp16 (resident) + small tables
    {
        const float4* src = (const float4*)g_w2h;
        float4*       dst = (float4*)(smem + SM_B);
        for (int i = tid; i < 256 * 528 / 16; i += 256) dst[i] = src[i];
    }
    float* w1t   = (float*)(smem + SM_W1T);
    float* b2s   = (float*)(smem + SM_B2S);
    float* w3s   = (float*)(smem + SM_W3S);
    float* slots = (float*)(smem + SM_SLOT);
    if (tid < 256) {
        w1t[tid] = W1[64 * 256 + tid];
        b2s[tid] = 30.0f * b2[tid];
        w3s[tid] = W3[tid];
    }
    __syncthreads();

    const float b3v = b3[0];

    const int wm = (w & 1) * 32;       // 2 m-groups x 32 rows
    const int wn = (w >> 1) * 64;      // 4 n-groups x 64 cols
    const int ng = w >> 1;

    const uint32_t a_toff = (uint32_t)(wm + (lane & 15)) * AROW + (uint32_t)(lane >> 4) * 16;
    const uint32_t b_toff = (uint32_t)(wn + (lane & 7) + ((lane >> 4) & 1) * 8) * AROW
                          + (uint32_t)((lane >> 3) & 1) * 16;
    const uint32_t b_base = sb + SM_B + b_toff;
    const uint32_t abuf[2] = {sb + SM_A0 + a_toff, sb + SM_A1 + a_toff};
    char* const   abufp[2] = {smem + SM_A0, smem + SM_A1};

    const int p1row = tid >> 2;          // 64 rows, 4 thr/row
    const int p1k   = (tid & 3) * 64;    // 64 k values per thread

    int tile = blockIdx.x;
    TP tp = make_tp(tcoord, tile);

    // Prologue: phase-1 for unit 0 (tile0, h=0) -> buf0
    {
        float4 a4[16];
        p1_load(a4, tp.slice, tp.pix0, p1row, p1k);
        char* wbase = abufp[0] + p1row * AROW + p1k * 2;
        #pragma unroll
        for (int j = 0; j < 16; j++) p1_chunk(wbase, w1t, tp.ctc, p1k, j, a4[j]);
    }
    __syncthreads();

    int bp = 0, par = 0;
    TP ntp = tp;

    #pragma unroll 1
    for (int u = 0; ; u++) {
        const int h = u & 1;

        // Next-unit parameters
        bool   more = true;
        size_t nslice;
        float  nctc;
        int    npix0;
        if (h == 0) {
            nslice = tp.slice + 1;  nctc = tp.ctc;  npix0 = tp.pix0;
        } else {
            int nt = tile + 148;
            more = (nt < 9216);
            if (more) ntp = make_tp(tcoord, nt);
            nslice = more ? ntp.slice : tp.slice;   // safe dummy when done
            nctc   = more ? ntp.ctc   : tp.ctc;
            npix0  = more ? ntp.pix0  : tp.pix0;
        }

        // Front-batched LDG of next unit's A rows
        float4 a4[16];
        p1_load(a4, nslice, npix0, p1row, p1k);

        // ---- fused K-loop: GEMM(buf[bp]) + phase-1 chunks -> buf[bp^1] ----
        float acc[2][8][4];
        #pragma unroll
        for (int mt = 0; mt < 2; mt++)
            #pragma unroll
            for (int nt = 0; nt < 8; nt++)
                #pragma unroll
                for (int c = 0; c < 4; c++) acc[mt][nt][c] = 0.0f;

        {
            uint32_t aaddr = abuf[bp], baddr = b_base;
            char* wbase = abufp[bp ^ 1] + p1row * AROW + p1k * 2;
            #pragma unroll
            for (int ks = 0; ks < 16; ks++) {
                uint32_t af0[4], af1[4];
                ldsm_x4(af0, aaddr);
                ldsm_x4(af1, aaddr + 16 * AROW);
                #pragma unroll
                for (int np = 0; np < 4; np++) {
                    uint32_t bf[4];
                    ldsm_x4(bf, baddr + np * 16 * AROW);
                    mma16816(acc[0][np * 2 + 0], af0, bf + 0);
                    mma16816(acc[0][np * 2 + 1], af0, bf + 2);
                    mma16816(acc[1][np * 2 + 0], af1, bf + 0);
                    mma16816(acc[1][np * 2 + 1], af1, bf + 2);
                }
                // interleaved phase-1 chunk (independent of acc -> fills gaps)
                p1_chunk(wbase, w1t, nctc, p1k, ks, a4[ks]);
                aaddr += 32;
                baddr += 32;
            }
        }

        // ---- epilogue: sin(30z + 30b2).W3, reduce -> slots[par][h] ----
        {
            float p[2][2];
            #pragma unroll
            for (int mt = 0; mt < 2; mt++)
                #pragma unroll
                for (int rh = 0; rh < 2; rh++) {
                    float s = 0.0f;
                    #pragma unroll
                    for (int nt = 0; nt < 8; nt++) {
                        int n0 = wn + nt * 8 + (lane & 3) * 2;
                        int c0 = rh * 2;
                        s = fmaf(__sinf(fmaf(30.0f, acc[mt][nt][c0],     b2s[n0]    )), w3s[n0],     s);
                        s = fmaf(__sinf(fmaf(30.0f, acc[mt][nt][c0 + 1], b2s[n0 + 1])), w3s[n0 + 1], s);
                    }
                    p[mt][rh] = s;
                }
            #pragma unroll
            for (int msk = 1; msk < 4; msk <<= 1) {
                #pragma unroll
                for (int mt = 0; mt < 2; mt++)
                    #pragma unroll
                    for (int rh = 0; rh < 2; rh++)
                        p[mt][rh] += __shfl_xor_sync(0xffffffffu, p[mt][rh], msk);
            }
            if ((lane & 3) == 0) {
                #pragma unroll
                for (int mt = 0; mt < 2; mt++)
                    #pragma unroll
                    for (int rh = 0; rh < 2; rh++)
                        slots[par * 512 + h * 256 + ng * 64 + wm + mt * 16 + rh * 8 + (lane >> 2)] = p[mt][rh];
            }
        }
        __syncthreads();
        bp ^= 1;

        if (h == 1) {
            // combine + output (parity-protected vs next tile's epilogues)
            if (tid < 64) {
                int sb0 = par * 512;
                float zf = slots[sb0 + tid]       + slots[sb0 + 64 + tid]
                         + slots[sb0 + 128 + tid] + slots[sb0 + 192 + tid];
                float zc = slots[sb0 + 256 + tid] + slots[sb0 + 320 + tid]
                         + slots[sb0 + 384 + tid] + slots[sb0 + 448 + tid];
                out[(size_t)tp.bq * HW + tp.pix0 + tid] = fmaf(tp.tau, zc - zf, zf) + b3v;
            }
            if (!more) break;
            tp = ntp;
            tile += 148;
            par ^= 1;
        }
    }
}

// ---------------------------------------------------------------------------
extern "C" void kernel_launch(void* const* d_in, const int* in_sizes, int n_in,
                              void* d_out, int out_size)
{
    const float* x_real  = (const float*)d_in[0];
    const float* x_imag  = (const float*)d_in[1];
    const float* t_coord = (const float*)d_in[2];
    const float* enc_w   = (const float*)d_in[3];
    const float* enc_b   = (const float*)d_in[4];
    const float* W1      = (const float*)d_in[5];
    const float* b1      = (const float*)d_in[6];
    const float* W2      = (const float*)d_in[7];
    const float* b2      = (const float*)d_in[8];
    const float* W3      = (const float*)d_in[9];
    const float* b3      = (const float*)d_in[10];
    float*       out     = (float*)d_out;

    size_t smem1 = (3456 + 64 + 256 * 65) * sizeof(float);
    cudaFuncSetAttribute(conv_kernel, cudaFuncAttributeMaxDynamicSharedMemorySize, (int)smem1);
    cudaFuncSetAttribute(proj_kernel, cudaFuncAttributeMaxDynamicSharedMemorySize, SMP_TOT);
    cudaFuncSetAttribute(main_kernel, cudaFuncAttributeMaxDynamicSharedMemorySize, SM_TOT);

    prep_w2<<<256, 256>>>(W2);
    prep_w1<<<256, 72>>>(W1);
    conv_kernel<<<2304, 256, smem1>>>(x_real, x_imag, enc_w, enc_b);
    proj_kernel<<<148, 512, SMP_TOT>>>(b1);
    main_kernel<<<148, 256, SM_TOT>>>(t_coord, W1, b2, W3, b3, out);
}

// round 17
// speedup vs baseline: 1.3026x; 1.0281x over previous
#include <cuda_runtime.h>
#include <cuda_fp16.h>
#include <cstdint>
#include <cstddef>

#define HW    9216      // 96*96
#define NCELL (2 * 32 * HW)   // 589824

// Scratch (device globals — allocation-free per harness rules)
__device__ float g_xenc[(size_t)NCELL * 64];       // conv output, channels-last
__device__ float g_A[(size_t)NCELL * 256];         // 30*(xenc @ W1[0:64] + b1)
__device__ __align__(16) __half g_w2s[256 * 256];  // W2^T fp16, [kchunk][n][16]
__device__ __align__(16) __half g_w1h[256 * 72];   // W1[0:64]^T hi fp16
__device__ __align__(16) __half g_w1l[256 * 72];   // W1[0:64]^T lo fp16

// ---------------------------------------------------------------------------
// Helpers
// ---------------------------------------------------------------------------
__device__ __forceinline__ uint32_t smem_u32(const void* p) {
    uint32_t a;
    asm("{ .reg .u64 t; cvta.to.shared.u64 t, %1; cvt.u32.u64 %0, t; }" : "=r"(a) : "l"(p));
    return a;
}
__device__ __forceinline__ void ldsm_x4(uint32_t (&r)[4], uint32_t addr) {
    asm volatile("ldmatrix.sync.aligned.m8n8.x4.shared.b16 {%0,%1,%2,%3}, [%4];"
                 : "=r"(r[0]), "=r"(r[1]), "=r"(r[2]), "=r"(r[3]) : "r"(addr));
}
__device__ __forceinline__ void mma16816(float (&d)[4], const uint32_t (&a)[4],
                                         const uint32_t* b) {
    asm volatile("mma.sync.aligned.m16n8k16.row.col.f32.f16.f16.f32 "
                 "{%0,%1,%2,%3}, {%4,%5,%6,%7}, {%8,%9}, {%0,%1,%2,%3};"
                 : "+f"(d[0]), "+f"(d[1]), "+f"(d[2]), "+f"(d[3])
                 : "r"(a[0]), "r"(a[1]), "r"(a[2]), "r"(a[3]), "r"(b[0]), "r"(b[1]));
}
__device__ __forceinline__ void cp_async16(uint32_t dst, const void* src) {
    asm volatile("cp.async.cg.shared.global [%0], [%1], 16;" :: "r"(dst), "l"(src));
}
__device__ __forceinline__ void cp_commit() {
    asm volatile("cp.async.commit_group;" ::: "memory");
}
__device__ __forceinline__ void cp_wait1() {
    asm volatile("cp.async.wait_group 1;" ::: "memory");
}
__device__ __forceinline__ void cp_wait0() {
    asm volatile("cp.async.wait_group 0;" ::: "memory");
}

// ---------------------------------------------------------------------------
// Kernel 1: 3D conv (2 -> 64 channels, 3x3x3, SAME), output channels-last.
// ---------------------------------------------------------------------------
__global__ __launch_bounds__(256) void conv_kernel(
    const float* __restrict__ xr, const float* __restrict__ xi,
    const float* __restrict__ ew, const float* __restrict__ eb)
{
    extern __shared__ float sm[];
    float* ws   = sm;            // 3456
    float* bs   = ws + 3456;     // 64
    float* tile = bs + 64;       // 256 * 65

    int tid = threadIdx.x;
    for (int e = tid; e < 3456; e += 256) ws[e] = ew[e];
    if (tid < 64) bs[tid] = eb[tid];

    int blk = blockIdx.x;
    int bt  = blk / 36;
    int t36 = blk % 36;
    int t   = bt & 31;
    int b   = bt >> 5;
    int pix = t36 * 256 + tid;
    int h   = pix / 96;
    int w   = pix % 96;

    float v[54];
    {
        int e = 0;
        #pragma unroll
        for (int ch = 0; ch < 2; ch++) {
            const float* src = (ch == 0) ? xr : xi;
            #pragma unroll
            for (int dt = -1; dt <= 1; dt++) {
                int  tt  = t + dt;
                bool okt = (tt >= 0) && (tt < 32);
                #pragma unroll
                for (int dh = -1; dh <= 1; dh++) {
                    int  hh  = h + dh;
                    bool okh = okt && (hh >= 0) && (hh < 96);
                    #pragma unroll
                    for (int dw = -1; dw <= 1; dw++) {
                        int  ww = w + dw;
                        bool ok = okh && (ww >= 0) && (ww < 96);
                        v[e++] = ok ? src[(((size_t)(b * 32 + tt)) * 96 + hh) * 96 + ww] : 0.0f;
                    }
                }
            }
        }
    }
    __syncthreads();

    #pragma unroll 4
    for (int c = 0; c < 64; c++) {
        float acc = bs[c];
        #pragma unroll
        for (int q = 0; q < 54; q++) acc = fmaf(v[q], ws[c * 54 + q], acc);
        tile[tid * 65 + c] = acc;
    }
    __syncthreads();

    size_t outbase = ((size_t)bt * HW + (size_t)t36 * 256) * 64;
    for (int e = tid; e < 256 * 64; e += 256) {
        int p = e >> 6, c = e & 63;
        g_xenc[outbase + e] = tile[p * 65 + c];
    }
}

// ---------------------------------------------------------------------------
// Prep kernels
// ---------------------------------------------------------------------------
// g_w2s layout: [kc 0..15][n 0..255][16 halves of k]
__global__ void prep_w2(const float* __restrict__ W2)
{
    int idx = blockIdx.x * 256 + threadIdx.x;   // 65536
    int n = idx >> 8, k = idx & 255;
    g_w2s[(((k >> 4) * 256 + n) << 4) + (k & 15)] = __float2half_rn(W2[k * 256 + n]);
}
__global__ void prep_w1(const float* __restrict__ W1)
{
    int n = blockIdx.x, k = threadIdx.x;        // 256 x 72
    float v = (k < 64) ? W1[k * 256 + n] : 0.0f;
    __half hi = __float2half_rn(v);
    g_w1h[n * 72 + k] = hi;
    g_w1l[n * 72 + k] = __float2half_rn(v - __half2float(hi));
}

// ---------------------------------------------------------------------------
// Kernel 2 (HMMA, persistent, 512 thr, prefetched): A = 30*(xenc@W1[0:64]+b1)
// ---------------------------------------------------------------------------
#define PROW 144              // bytes per [.,72-half] row
#define SMP_WH 0              // 256*144 = 36864
#define SMP_WL 36864
#define SMP_XH 73728          // 64*144 = 9216
#define SMP_XL 82944
#define SMP_TOT 92160

__global__ __launch_bounds__(512, 1) void proj_kernel(
    const float* __restrict__ b1)
{
    extern __shared__ char smem[];
    const uint32_t sb = smem_u32(smem);
    int tid  = threadIdx.x;
    int w    = tid >> 5;
    int lane = tid & 31;

    // Stage W1 hi/lo (resident)
    {
        const float4* s0 = (const float4*)g_w1h;
        const float4* s1 = (const float4*)g_w1l;
        float4* d0 = (float4*)(smem + SMP_WH);
        float4* d1 = (float4*)(smem + SMP_WL);
        for (int i = tid; i < 256 * 144 / 16; i += 512) { d0[i] = s0[i]; d1[i] = s1[i]; }
    }

    const int wm = (w & 3) * 16;       // 4 m-groups x 16 rows
    const int wn = (w >> 2) * 64;      // 4 n-groups x 64 cols

    float b1r[16];
    #pragma unroll
    for (int q = 0; q < 16; q++)
        b1r[q] = b1[wn + (q >> 1) * 8 + (lane & 3) * 2 + (q & 1)];

    const uint32_t a_toff = (uint32_t)(wm + (lane & 15)) * PROW + (uint32_t)(lane >> 4) * 16;
    const uint32_t b_toff = (uint32_t)(wn + (lane & 7) + ((lane >> 4) & 1) * 8) * PROW
                          + (uint32_t)((lane >> 3) & 1) * 16;

    const int lrow = tid >> 3;             // cell row this thread loads (64 rows)
    const int lk   = (tid & 7) * 8;        // 8 k values
    __syncthreads();

    // Prologue prefetch
    float4 v0, v1;
    {
        const float4* src = (const float4*)(g_xenc + ((size_t)blockIdx.x * 64 + lrow) * 64 + lk);
        v0 = src[0]; v1 = src[1];
    }

    for (int tile = blockIdx.x; tile < 9216; tile += 148) {
        size_t cell0 = (size_t)tile * 64;

        // Split held regs -> smem
        {
            float vv[8] = {v0.x, v0.y, v0.z, v0.w, v1.x, v1.y, v1.z, v1.w};
            uint32_t hv[4], lv[4];
            #pragma unroll
            for (int p = 0; p < 4; p++) {
                __half h0 = __float2half_rn(vv[2*p]),   h1 = __float2half_rn(vv[2*p+1]);
                __half l0 = __float2half_rn(vv[2*p]   - __half2float(h0));
                __half l1 = __float2half_rn(vv[2*p+1] - __half2float(h1));
                __half2 ph = __halves2half2(h0, h1), pl = __halves2half2(l0, l1);
                hv[p] = *(uint32_t*)&ph;  lv[p] = *(uint32_t*)&pl;
            }
            *(uint4*)(smem + SMP_XH + lrow * PROW + lk * 2) = make_uint4(hv[0], hv[1], hv[2], hv[3]);
            *(uint4*)(smem + SMP_XL + lrow * PROW + lk * 2) = make_uint4(lv[0], lv[1], lv[2], lv[3]);
        }
        __syncthreads();

        // Prefetch next tile while GEMM runs
        int ntile = tile + 148;
        if (ntile < 9216) {
            const float4* src = (const float4*)(g_xenc + ((size_t)ntile * 64 + lrow) * 64 + lk);
            v0 = src[0]; v1 = src[1];
        }

        float acc[8][4];
        #pragma unroll
        for (int nt = 0; nt < 8; nt++)
            #pragma unroll
            for (int c = 0; c < 4; c++) acc[nt][c] = 0.0f;

        const uint32_t abase[3] = {sb + SMP_XH, sb + SMP_XL, sb + SMP_XH};
        const uint32_t bbase[3] = {sb + SMP_WH, sb + SMP_WH, sb + SMP_WL};
        #pragma unroll
        for (int s = 0; s < 3; s++) {
            uint32_t a_addr = abase[s] + a_toff;
            uint32_t b_addr = bbase[s] + b_toff;
            #pragma unroll
            for (int ks = 0; ks < 4; ks++) {
                uint32_t af[4];
                ldsm_x4(af, a_addr);
                #pragma unroll
                for (int np = 0; np < 4; np++) {
                    uint32_t bf[4];
                    ldsm_x4(bf, b_addr + np * 16 * PROW);
                    mma16816(acc[np * 2 + 0], af, bf + 0);
                    mma16816(acc[np * 2 + 1], af, bf + 2);
                }
                a_addr += 32;
                b_addr += 32;
            }
        }

        // Epilogue: A = 30*(z1 + b1), direct STG.64
        {
            int r0 = wm + (lane >> 2);
            #pragma unroll
            for (int nt = 0; nt < 8; nt++) {
                int n0 = wn + nt * 8 + (lane & 3) * 2;
                float2 o0, o1;
                o0.x = 30.0f * (acc[nt][0] + b1r[nt*2+0]);
                o0.y = 30.0f * (acc[nt][1] + b1r[nt*2+1]);
                o1.x = 30.0f * (acc[nt][2] + b1r[nt*2+0]);
                o1.y = 30.0f * (acc[nt][3] + b1r[nt*2+1]);
                *(float2*)&g_A[(cell0 + r0)     * 256 + n0] = o0;
                *(float2*)&g_A[(cell0 + r0 + 8) * 256 + n0] = o1;
            }
        }
        __syncthreads();
    }
}

// ---------------------------------------------------------------------------
// Kernel 3: persistent HMMA SIREN, 296 CTAs (2/SM via 64KB smem), 256 thr.
// W2 streamed per K-chunk from L2 via warp-private double-buffered cp.async
// (no CTA barriers in the K-loop). Warp tile: all 64 rows x 32 cols.
// Per tile: [p1 h0; sync; GEMM+epi h0; sync; p1 h1; sync; GEMM+epi h1; sync;
// combine]. Cross-CTA overlap (2/SM) hides MUFU vs tensor vs memory.
// ---------------------------------------------------------------------------
#define AROW    528           // bytes per [.,264-half] A row
#define SMN_A    0            // 64*528 = 33792
#define SMN_W2S  33792        // 8 warps * 2 stages * 1536 = 24576
#define SMN_W1T  58368        // 1024
#define SMN_B2S  59392        // 1024
#define SMN_W3S  60416        // 1024
#define SMN_SLOT 61440        // 2h * 512 floats = 4096
#define SMN_TOT  65536

struct TP { size_t slice; float tau, ctc; int bq, pix0; };

__device__ __forceinline__ TP make_tp(const float* __restrict__ tcoord, int tile)
{
    TP t;
    t.bq  = tile & 63;
    t.pix0 = (tile >> 6) * 64;
    int b = t.bq >> 5;
    float tc = tcoord[t.bq];
    tc = fminf(fmaxf(tc, -1.0f), 1.0f - 1e-6f);
    const float df = 2.0f / 31.0f;
    int ti = (int)floorf((tc + 1.0f) / df);
    t.tau = (tc - (-1.0f + (float)ti * df)) / df;
    t.ctc = 30.0f * tc;
    t.slice = (size_t)(b * 32 + ti);
    return t;
}

// phase1: h1 = sin(A + ctc*w1t) -> fp16 -> A smem (row, k in [kbase,kbase+64))
__device__ __forceinline__ void phase1(char* __restrict__ abuf,
    const float* __restrict__ w1t, size_t slice, int pix0, float ctc,
    int row, int kbase)
{
    const float4* s4 = (const float4*)(g_A + (slice * HW + pix0 + row) * 256 + kbase);
    char* hb = abuf + row * AROW + kbase * 2;
    #pragma unroll
    for (int c = 0; c < 2; c++) {
        float4 a4[8];
        #pragma unroll
        for (int j = 0; j < 8; j++) a4[j] = s4[c * 8 + j];
        #pragma unroll
        for (int j = 0; j < 8; j++) {
            const float4 wv = *(const float4*)&w1t[kbase + c * 32 + 4 * j];
            float s0 = __sinf(fmaf(ctc, wv.x, a4[j].x));
            float s1 = __sinf(fmaf(ctc, wv.y, a4[j].y));
            float s2 = __sinf(fmaf(ctc, wv.z, a4[j].z));
            float s3 = __sinf(fmaf(ctc, wv.w, a4[j].w));
            __half2 p0 = __halves2half2(__float2half_rn(s0), __float2half_rn(s1));
            __half2 p1 = __halves2half2(__float2half_rn(s2), __float2half_rn(s3));
            *(uint2*)(hb + c * 64 + j * 8) = make_uint2(*(uint32_t*)&p0, *(uint32_t*)&p1);
        }
    }
}

__global__ __launch_bounds__(256, 2) void main_kernel(
    const float* __restrict__ tcoord, const float* __restrict__ W1,
    const float* __restrict__ b2, const float* __restrict__ W3,
    const float* __restrict__ b3, float* __restrict__ out)
{
    extern __shared__ char smem[];
    const uint32_t sb = smem_u32(smem);
    int tid  = threadIdx.x;
    int w    = tid >> 5;
    int lane = tid & 31;

    float* w1t   = (float*)(smem + SMN_W1T);
    float* b2s   = (float*)(smem + SMN_B2S);
    float* w3s   = (float*)(smem + SMN_W3S);
    float* slots = (float*)(smem + SMN_SLOT);
    if (tid < 256) {
        w1t[tid] = W1[64 * 256 + tid];
        b2s[tid] = 30.0f * b2[tid];
        w3s[tid] = W3[tid];
    }
    __syncthreads();

    const float b3v = b3[0];
    const int   wn  = w * 32;          // warp-private 32-col slice

    // A fragment per-thread offset (rows lane&15, col seg (lane>>4)*16B)
    const uint32_t a_toff = (uint32_t)(lane & 15) * AROW + (uint32_t)(lane >> 4) * 16;
    // B fragment per-thread offset in warp stage buffer (48B rows)
    const uint32_t bl_off = (uint32_t)((lane & 7) + ((lane >> 4) & 1) * 8) * 48
                          + (uint32_t)((lane >> 3) & 1) * 16;
    // cp.async per-lane offsets
    const uint32_t cp_d0 = (uint32_t)(lane >> 1) * 48 + (uint32_t)(lane & 1) * 16;
    const uint32_t cp_d1 = cp_d0 + 16 * 48;
    const uint32_t stg0  = sb + SMN_W2S + (uint32_t)w * 3072;
    const uint32_t stg1  = stg0 + 1536;
    const char*    w2src = (const char*)g_w2s + wn * 32 + lane * 16;

    const int p1row = tid >> 2;          // 64 rows, 4 thr/row
    const int p1k   = (tid & 3) * 64;    // 64 k values per thread

    for (int tile = blockIdx.x; tile < 9216; tile += 296) {
        TP tp = make_tp(tcoord, tile);

        #pragma unroll 1
        for (int h = 0; h < 2; h++) {
            // ---- phase 1 ----
            phase1(smem + SMN_A, w1t, tp.slice + h, tp.pix0, tp.ctc, p1row, p1k);
            __syncthreads();

            // ---- GEMM: 64 x 32(warp) x 256, W2 streamed via cp.async ----
            float acc[4][4][4];
            #pragma unroll
            for (int mf = 0; mf < 4; mf++)
                #pragma unroll
                for (int nf = 0; nf < 4; nf++)
                    #pragma unroll
                    for (int c = 0; c < 4; c++) acc[mf][nf][c] = 0.0f;

            // prologue: stage chunk 0
            cp_async16(stg0 + cp_d0, w2src);
            cp_async16(stg0 + cp_d1, w2src + 512);
            cp_commit();

            #pragma unroll 4
            for (int ks = 0; ks < 16; ks++) {
                const uint32_t stg_cur = (ks & 1) ? stg1 : stg0;
                if (ks < 15) {
                    const uint32_t stg_nxt = (ks & 1) ? stg0 : stg1;
                    const char* src = w2src + (ks + 1) * 8192;
                    cp_async16(stg_nxt + cp_d0, src);
                    cp_async16(stg_nxt + cp_d1, src + 512);
                    cp_commit();
                    cp_wait1();
                } else {
                    cp_wait0();
                }
                __syncwarp();

                uint32_t bf0[4], bf1[4];
                ldsm_x4(bf0, stg_cur + bl_off);
                ldsm_x4(bf1, stg_cur + bl_off + 16 * 48);
                uint32_t a_addr = sb + SMN_A + a_toff + ks * 32;
                #pragma unroll
                for (int mf = 0; mf < 4; mf++) {
                    uint32_t af[4];
                    ldsm_x4(af, a_addr + mf * 16 * AROW);
                    mma16816(acc[mf][0], af, bf0 + 0);
                    mma16816(acc[mf][1], af, bf0 + 2);
                    mma16816(acc[mf][2], af, bf1 + 0);
                    mma16816(acc[mf][3], af, bf1 + 2);
                }
            }

            // ---- epilogue: sin(30z + 30b2).W3 partial dot over 32 cols ----
            #pragma unroll
            for (int mf = 0; mf < 4; mf++) {
                float p0 = 0.0f, p1v = 0.0f;
                #pragma unroll
                for (int nf = 0; nf < 4; nf++) {
                    int n0 = wn + nf * 8 + (lane & 3) * 2;
                    p0  = fmaf(__sinf(fmaf(30.0f, acc[mf][nf][0], b2s[n0]    )), w3s[n0],     p0);
                    p0  = fmaf(__sinf(fmaf(30.0f, acc[mf][nf][1], b2s[n0 + 1])), w3s[n0 + 1], p0);
                    p1v = fmaf(__sinf(fmaf(30.0f, acc[mf][nf][2], b2s[n0]    )), w3s[n0],     p1v);
                    p1v = fmaf(__sinf(fmaf(30.0f, acc[mf][nf][3], b2s[n0 + 1])), w3s[n0 + 1], p1v);
                }
                p0  += __shfl_xor_sync(0xffffffffu, p0, 1);
                p0  += __shfl_xor_sync(0xffffffffu, p0, 2);
                p1v += __shfl_xor_sync(0xffffffffu, p1v, 1);
                p1v += __shfl_xor_sync(0xffffffffu, p1v, 2);
                if ((lane & 3) == 0) {
                    slots[h * 512 + w * 64 + mf * 16 + (lane >> 2)]     = p0;
                    slots[h * 512 + w * 64 + mf * 16 + 8 + (lane >> 2)] = p1v;
                }
            }
            __syncthreads();
        }

        // ---- combine + output ----
        if (tid < 64) {
            float zf = 0.0f, zc = 0.0f;
            #pragma unroll
            for (int ww = 0; ww < 8; ww++) {
                zf += slots[ww * 64 + tid];
                zc += slots[512 + ww * 64 + tid];
            }
            out[(size_t)tp.bq * HW + tp.pix0 + tid] = fmaf(tp.tau, zc - zf, zf) + b3v;
        }
        // next iteration's phase1 writes A (not slots); slots are next written
        // only after a GEMM that follows a __syncthreads -> no race.
    }
}

// ---------------------------------------------------------------------------
extern "C" void kernel_launch(void* const* d_in, const int* in_sizes, int n_in,
                              void* d_out, int out_size)
{
    const float* x_real  = (const float*)d_in[0];
    const float* x_imag  = (const float*)d_in[1];
    const float* t_coord = (const float*)d_in[2];
    const float* enc_w   = (const float*)d_in[3];
    const float* enc_b   = (const float*)d_in[4];
    const float* W1      = (const float*)d_in[5];
    const float* b1      = (const float*)d_in[6];
    const float* W2      = (const float*)d_in[7];
    const float* b2      = (const float*)d_in[8];
    const float* W3      = (const float*)d_in[9];
    const float* b3      = (const float*)d_in[10];
    float*       out     = (float*)d_out;

    size_t smem1 = (3456 + 64 + 256 * 65) * sizeof(float);
    cudaFuncSetAttribute(conv_kernel, cudaFuncAttributeMaxDynamicSharedMemorySize, (int)smem1);
    cudaFuncSetAttribute(proj_kernel, cudaFuncAttributeMaxDynamicSharedMemorySize, SMP_TOT);
    cudaFuncSetAttribute(main_kernel, cudaFuncAttributeMaxDynamicSharedMemorySize, SMN_TOT);

    prep_w2<<<256, 256>>>(W2);
    prep_w1<<<256, 72>>>(W1);
    conv_kernel<<<2304, 256, smem1>>>(x_real, x_imag, enc_w, enc_b);
    proj_kernel<<<148, 512, SMP_TOT>>>(b1);
    main_kernel<<<296, 256, SMN_TOT>>>(t_coord, W1, b2, W3, b3, out);
}